// round 14
// baseline (speedup 1.0000x reference)
#include <cuda_runtime.h>
#include <math.h>

#define BB 2
#define HH 80
#define WW 80
#define NPIX (HH * WW)

#define TW 16              // tile width (cols); one thread-col per jx
#define TH 8               // tile height (rows); 2 rgrp * 4 pixels
#define NPH 16             // phases = window columns (2W+1 active)
#define NTHR 512
#define NWARP 16
#define NPIXT (TW * TH)    // 128 pixels per block
#define PAD 6              // speculative region padding (covers R<=6)
#define RGH (TH + 2 * PAD) // 20
#define RGW (TW + 2 * PAD) // 28  (560 region cells)
#define RMAX 16            // dynamic SMEM path up to here; full scan beyond
#define DSTRIDE (TW + 2 * RMAX)   // 48 (dynamic-path row stride)
#define PMW 160            // s_pmin phase stride (conflict-padded)
#define BIGE 3.0e30f

__device__ __forceinline__ float4 center_coef(float v0, float v1, float v2, float sg) {
    float vh = fmaxf(v0, 0.0f) + 1.0f;
    float vw = fmaxf(v1, 0.0f) + 1.0f;
    float theta = __fdividef(3.14f, 1.0f + __expf(-v2));   // 3.14 * sigmoid(v2)
    float s, co;
    __sincosf(theta, &s, &co);
    float ivh2 = __fdividef(0.5f, vh * vh);                // 1/(2 vh^2)
    float ivw2 = __fdividef(0.5f, vw * vw);                // 1/(2 vw^2)
    float a  = co * co * ivh2 + s * s * ivw2;
    float b2 = 2.0f * s * co * (ivw2 - ivh2);              // 2*b of reference
    float c  = s * s * ivh2 + co * co * ivw2;
    float pen = (sg > 0.7f) ? 0.0f : BIGE;
    return make_float4(a, b2, c, pen);
}

// Window over the PAD=6 region with radius W<=6 (R11-proven form).
// Thread = (jx, rgrp, tz): window column c = jx + (PAD-W) + tz for 4 pixels
// (rows rgrp*4..+3, col jx). dy uniform; dx compile-time -> FFMA-imm.
// Each cell float4 loaded once serves 4 pixels.
template <int W>
__device__ __forceinline__ void fast_window(const float4* __restrict__ s_coef,
                                            float* __restrict__ s_pmin,
                                            int jx, int rgrp, int tz) {
    float m0 = BIGE, m1 = BIGE, m2 = BIGE, m3 = BIGE;
    if (tz <= 2 * W) {
        const float dy = (float)(W - tz);
        const float dy2 = dy * dy;
        const float4* col = s_coef + (rgrp * 4 + PAD - W) * RGW + jx + (PAD - W) + tz;
        #pragma unroll
        for (int ci = 0; ci < 4 + 2 * W; ci++) {
            float4 k = col[ci * RGW];
            float s0 = fmaf(k.z, dy2, k.w);     // c*dy^2 + penalty
            float t  = k.y * dy;                // 2b*dy
            { const float dx = (float)(W + 0 - ci);
              m0 = fminf(m0, fmaf(fmaf(k.x, dx, t), dx, s0)); }
            { const float dx = (float)(W + 1 - ci);
              m1 = fminf(m1, fmaf(fmaf(k.x, dx, t), dx, s0)); }
            { const float dx = (float)(W + 2 - ci);
              m2 = fminf(m2, fmaf(fmaf(k.x, dx, t), dx, s0)); }
            { const float dx = (float)(W + 3 - ci);
              m3 = fminf(m3, fmaf(fmaf(k.x, dx, t), dx, s0)); }
        }
    }
    float* pm = s_pmin + tz * PMW + rgrp * 80 + jx;
    pm[0]  = m0;
    pm[16] = m1;
    pm[32] = m2;
    pm[48] = m3;
}

__global__ void __launch_bounds__(NTHR) fused_tile_kernel(const float* __restrict__ var,
                                                          const float* __restrict__ seg,
                                                          float* __restrict__ out) {
    __shared__ float4 s_coef[(TH + 2 * RMAX) * DSTRIDE];   // 30.7 KB (worst case)
    __shared__ float s_red[NWARP];
    __shared__ float s_pmin[NPH * PMW];                     // 10.2 KB

    const int jx   = threadIdx.x;               // 0..15 (tile col)
    const int rgrp = threadIdx.y;               // 0..1  (4-row pixel group)
    const int tz   = threadIdx.z;               // 0..15 (window-col phase)
    const int tid  = tz * 32 + rgrp * 16 + jx;
    const int b  = blockIdx.z;
    const int i0 = blockIdx.y * TH;
    const int j0 = blockIdx.x * TW;
    const float* vb = var + b * 3 * NPIX;
    const float* sb = seg + b * NPIX;

    // ---- 1a. SPECULATIVE fill of the PAD=6 region (R-independent layout). ----
    // Values die at the STS -> no register pressure carried across the barrier.
    for (int k = tid; k < RGH * RGW; k += NTHR) {
        int rr = k / RGW;                       // compile-time RGW -> mul/shift
        int cc = k - rr * RGW;
        int r = i0 - PAD + rr;
        int c = j0 - PAD + cc;
        float4 v;
        if (r >= 0 && r < HH && c >= 0 && c < WW) {
            int g = r * WW + c;
            v = center_coef(vb[g], vb[NPIX + g], vb[2 * NPIX + g], sb[g]);
        } else {
            v = make_float4(0.0f, 0.0f, 0.0f, BIGE);
        }
        s_coef[k] = v;
    }

    // ---- 1b. vmax over this batch's channels 0,1: 3200 float4 = 512*6 + 128 ----
    {
        const float4* v4 = reinterpret_cast<const float4*>(vb);
        float4 x[7];
        #pragma unroll
        for (int u = 0; u < 6; u++) x[u] = v4[tid + u * NTHR];
        bool extra = tid < 128;
        if (extra) x[6] = v4[3072 + tid];
        float m = 0.0f;
        #pragma unroll
        for (int u = 0; u < 6; u++)
            m = fmaxf(m, fmaxf(fmaxf(x[u].x, x[u].y), fmaxf(x[u].z, x[u].w)));
        if (extra)
            m = fmaxf(m, fmaxf(fmaxf(x[6].x, x[6].y), fmaxf(x[6].z, x[6].w)));
        m = __uint_as_float(__reduce_max_sync(0xFFFFFFFFu, __float_as_uint(m)));
        if ((tid & 31) == 0) s_red[tid >> 5] = m;
    }

    // ---- single barrier: covers region fill AND s_red publication ----
    __syncthreads();

    float vmax;
    {
        float bm = s_red[0];
        #pragma unroll
        for (int w = 1; w < NWARP; w++) bm = fmaxf(bm, s_red[w]);
        vmax = fmaxf(bm, 0.0f) + 1.0f;
    }

    // E >= r^2/(2*vmax^2); relevant only if E <= -ln(0.7) ~ 0.356676 -> r <= 0.84460*vmax
    int R = (int)(0.84461f * vmax) + 1;

    if (R <= 5) {
        fast_window<5>(s_coef, s_pmin, jx, rgrp, tz);
    } else if (R <= PAD) {
        fast_window<6>(s_coef, s_pmin, jx, rgrp, tz);
    } else if (R <= RMAX) {
        // ---- dynamic-bounds SMEM path (rare): rebuild s_coef in its own layout ----
        __syncthreads();                        // everyone done with speculative data
        const int r0 = max(i0 - R, 0), r1 = min(i0 + TH - 1 + R, HH - 1);
        const int c0 = max(j0 - R, 0), c1 = min(j0 + TW - 1 + R, WW - 1);
        const int rh = r1 - r0 + 1, rw = c1 - c0 + 1;
        for (int k = tid; k < rh * rw; k += NTHR) {
            int rr = k / rw;
            int cc = k - rr * rw;
            int g = (r0 + rr) * WW + (c0 + cc);
            s_coef[rr * DSTRIDE + cc] =
                center_coef(vb[g], vb[NPIX + g], vb[2 * NPIX + g], sb[g]);
        }
        __syncthreads();
        const int j = j0 + jx;
        const int wc0 = max(j - R, 0), wc1 = min(j + R, WW - 1);
        float pm4[4];
        #pragma unroll
        for (int pi = 0; pi < 4; pi++) {
            int i = i0 + rgrp * 4 + pi;
            int wr0 = max(i - R, 0), wr1 = min(i + R, HH - 1);
            float m = BIGE;
            for (int r = wr0 + tz; r <= wr1; r += NPH) {
                float dx = (float)(i - r);
                float dx2 = dx * dx;
                const float4* row = s_coef + (r - r0) * DSTRIDE - c0;
                for (int cc = wc0; cc <= wc1; cc++) {
                    float4 k = row[cc];
                    float dy = (float)(j - cc);
                    float E = fmaf(k.x, dx2, k.w);
                    E = fmaf(k.y, dx * dy, E);
                    E = fmaf(k.z, dy * dy, E);
                    m = fminf(m, E);
                }
            }
            pm4[pi] = m;
        }
        float* pm = s_pmin + tz * PMW + rgrp * 80 + jx;
        pm[0] = pm4[0]; pm[16] = pm4[1]; pm[32] = pm4[2]; pm[48] = pm4[3];
    } else {
        // ---- slow path (never for sane inputs): full scan, on-the-fly coef ----
        const int j = j0 + jx;
        float pm4[4] = {BIGE, BIGE, BIGE, BIGE};
        for (int r = tz; r < HH; r += NPH) {
            float dxs[4];
            #pragma unroll
            for (int pi = 0; pi < 4; pi++) dxs[pi] = (float)(i0 + rgrp * 4 + pi - r);
            for (int cc = 0; cc < WW; cc++) {
                int g = r * WW + cc;
                float4 k = center_coef(vb[g], vb[NPIX + g], vb[2 * NPIX + g], sb[g]);
                float dy = (float)(j - cc);
                float s0 = fmaf(k.z, dy * dy, k.w);
                float t  = k.y * dy;
                #pragma unroll
                for (int pi = 0; pi < 4; pi++)
                    pm4[pi] = fminf(pm4[pi], fmaf(fmaf(k.x, dxs[pi], t), dxs[pi], s0));
            }
        }
        float* pm = s_pmin + tz * PMW + rgrp * 80 + jx;
        pm[0] = pm4[0]; pm[16] = pm4[1]; pm[32] = pm4[2]; pm[48] = pm4[3];
    }

    // ---- combine 16 phase partials per pixel, exp + threshold, store ----
    __syncthreads();
    if (tid < NPIXT) {
        int phys = tid + (tid >> 6) * 16;       // rgrp*80 + pi*16 + jx
        float m = s_pmin[phys];
        #pragma unroll
        for (int ph = 1; ph < NPH; ph++) m = fminf(m, s_pmin[ph * PMW + phys]);
        float pooled = __expf(1e-7f - m);       // exp(-minE + eps)
        int ti = tid >> 4, tj = tid & 15;
        out[(b * HH + i0 + ti) * WW + j0 + tj] = (pooled >= 0.7f) ? pooled : 0.0f;
    }
}

extern "C" void kernel_launch(void* const* d_in, const int* in_sizes, int n_in,
                              void* d_out, int out_size) {
    const float* var = (const float*)d_in[0];   // [2,3,80,80]
    const float* seg = (const float*)d_in[1];   // [2,1,80,80]
    float* out = (float*)d_out;                 // [2,1,80,80]
    fused_tile_kernel<<<dim3(WW / TW, HH / TH, BB), dim3(TW, 2, NPH)>>>(var, seg, out);
}

// round 15
// speedup vs baseline: 1.0933x; 1.0933x over previous
#include <cuda_runtime.h>
#include <math.h>

#define BB 2
#define HH 80
#define WW 80
#define NPIX (HH * WW)

#define TW 16              // tile width (cols); one thread-col per jx
#define TH 8               // tile height (rows); 2 rgrp * 4 pixels
#define NPH 16             // phases = window columns (2W+1 active)
#define NTHR 512
#define NWARP 16
#define NPIXT (TW * TH)    // 128 pixels per block
#define PAD 5              // speculative region padding (covers R<=5; 468 cells <= 512 thr)
#define RGH (TH + 2 * PAD) // 18
#define RGW (TW + 2 * PAD) // 26  (468 region cells -> exactly <=1 coef chain/thread)
#define RMAX 16            // dynamic SMEM path up to here; full scan beyond
#define DSTRIDE (TW + 2 * RMAX)   // 48 (dynamic-path row stride)
#define PMW 160            // s_pmin phase stride (conflict-padded)
#define BIGE 3.0e30f

__device__ __forceinline__ float4 center_coef(float v0, float v1, float v2, float sg) {
    float vh = fmaxf(v0, 0.0f) + 1.0f;
    float vw = fmaxf(v1, 0.0f) + 1.0f;
    float theta = __fdividef(3.14f, 1.0f + __expf(-v2));   // 3.14 * sigmoid(v2)
    float s, co;
    __sincosf(theta, &s, &co);
    float ivh2 = __fdividef(0.5f, vh * vh);                // 1/(2 vh^2)
    float ivw2 = __fdividef(0.5f, vw * vw);                // 1/(2 vw^2)
    float a  = co * co * ivh2 + s * s * ivw2;
    float b2 = 2.0f * s * co * (ivw2 - ivh2);              // 2*b of reference
    float c  = s * s * ivh2 + co * co * ivw2;
    float pen = (sg > 0.7f) ? 0.0f : BIGE;
    return make_float4(a, b2, c, pen);
}

// Window over the PAD=5 region, radius W=5. Thread = (jx, rgrp, tz): window
// column c = jx + tz for 4 pixels (rows rgrp*4..+3, col jx). dy uniform per
// thread; dx compile-time -> FFMA-imm. Triangular mask: cell ci belongs to
// pixel pi's window iff pi <= ci <= pi+2W (compile-time; drops 12/56 evals).
__device__ __forceinline__ void fast_window5(const float4* __restrict__ s_coef,
                                             float* __restrict__ s_pmin,
                                             int jx, int rgrp, int tz) {
    constexpr int W = PAD;                      // 5
    float m0 = BIGE, m1 = BIGE, m2 = BIGE, m3 = BIGE;
    if (tz <= 2 * W) {
        const float dy = (float)(W - tz);
        const float dy2 = dy * dy;
        const float4* col = s_coef + (rgrp * 4) * RGW + jx + tz;
        #pragma unroll
        for (int ci = 0; ci < 4 + 2 * W; ci++) {
            float4 k = col[ci * RGW];
            float s0 = fmaf(k.z, dy2, k.w);     // c*dy^2 + penalty
            float t  = k.y * dy;                // 2b*dy
            if (ci >= 0 && ci <= 0 + 2 * W) { const float dx = (float)(W + 0 - ci);
                m0 = fminf(m0, fmaf(fmaf(k.x, dx, t), dx, s0)); }
            if (ci >= 1 && ci <= 1 + 2 * W) { const float dx = (float)(W + 1 - ci);
                m1 = fminf(m1, fmaf(fmaf(k.x, dx, t), dx, s0)); }
            if (ci >= 2 && ci <= 2 + 2 * W) { const float dx = (float)(W + 2 - ci);
                m2 = fminf(m2, fmaf(fmaf(k.x, dx, t), dx, s0)); }
            if (ci >= 3 && ci <= 3 + 2 * W) { const float dx = (float)(W + 3 - ci);
                m3 = fminf(m3, fmaf(fmaf(k.x, dx, t), dx, s0)); }
        }
    }
    float* pm = s_pmin + tz * PMW + rgrp * 80 + jx;
    pm[0]  = m0;
    pm[16] = m1;
    pm[32] = m2;
    pm[48] = m3;
}

__global__ void __launch_bounds__(NTHR) fused_tile_kernel(const float* __restrict__ var,
                                                          const float* __restrict__ seg,
                                                          float* __restrict__ out) {
    __shared__ float4 s_coef[(TH + 2 * RMAX) * DSTRIDE];   // 30.7 KB (worst case)
    __shared__ float s_red[NWARP];
    __shared__ float s_pmin[NPH * PMW];                     // 10.2 KB

    const int jx   = threadIdx.x;               // 0..15 (tile col)
    const int rgrp = threadIdx.y;               // 0..1  (4-row pixel group)
    const int tz   = threadIdx.z;               // 0..15 (window-col phase)
    const int tid  = tz * 32 + rgrp * 16 + jx;
    const int b  = blockIdx.z;
    const int i0 = blockIdx.y * TH;
    const int j0 = blockIdx.x * TW;
    const float* vb = var + b * 3 * NPIX;
    const float* sb = seg + b * NPIX;

    // ---- 1a. SPECULATIVE fill of the PAD=5 region: ONE cell per thread. ----
    // Values die at the STS -> no register pressure carried across the barrier.
    if (tid < RGH * RGW) {
        int rr = tid / RGW;
        int cc = tid - rr * RGW;
        int r = i0 - PAD + rr;
        int c = j0 - PAD + cc;
        float4 v;
        if (r >= 0 && r < HH && c >= 0 && c < WW) {
            int g = r * WW + c;
            v = center_coef(vb[g], vb[NPIX + g], vb[2 * NPIX + g], sb[g]);
        } else {
            v = make_float4(0.0f, 0.0f, 0.0f, BIGE);
        }
        s_coef[tid] = v;
    }

    // ---- 1b. vmax over this batch's channels 0,1: 3200 float4 = 512*6 + 128 ----
    {
        const float4* v4 = reinterpret_cast<const float4*>(vb);
        float4 x[7];
        #pragma unroll
        for (int u = 0; u < 6; u++) x[u] = v4[tid + u * NTHR];
        bool extra = tid < 128;
        if (extra) x[6] = v4[3072 + tid];
        float m = 0.0f;
        #pragma unroll
        for (int u = 0; u < 6; u++)
            m = fmaxf(m, fmaxf(fmaxf(x[u].x, x[u].y), fmaxf(x[u].z, x[u].w)));
        if (extra)
            m = fmaxf(m, fmaxf(fmaxf(x[6].x, x[6].y), fmaxf(x[6].z, x[6].w)));
        m = __uint_as_float(__reduce_max_sync(0xFFFFFFFFu, __float_as_uint(m)));
        if ((tid & 31) == 0) s_red[tid >> 5] = m;
    }

    // ---- single barrier: covers region fill AND s_red publication ----
    __syncthreads();

    float vmax;
    {
        float bm = s_red[0];
        #pragma unroll
        for (int w = 1; w < NWARP; w++) bm = fmaxf(bm, s_red[w]);
        vmax = fmaxf(bm, 0.0f) + 1.0f;
    }

    // E >= r^2/(2*vmax^2); relevant only if E <= -ln(0.7) ~ 0.356676 -> r <= 0.84460*vmax
    int R = (int)(0.84461f * vmax) + 1;

    if (R <= PAD) {
        fast_window5(s_coef, s_pmin, jx, rgrp, tz);
    } else if (R <= RMAX) {
        // ---- dynamic-bounds SMEM path (rare): rebuild s_coef in its own layout ----
        __syncthreads();                        // everyone done with speculative data
        const int r0 = max(i0 - R, 0), r1 = min(i0 + TH - 1 + R, HH - 1);
        const int c0 = max(j0 - R, 0), c1 = min(j0 + TW - 1 + R, WW - 1);
        const int rh = r1 - r0 + 1, rw = c1 - c0 + 1;
        for (int k = tid; k < rh * rw; k += NTHR) {
            int rr = k / rw;
            int cc = k - rr * rw;
            int g = (r0 + rr) * WW + (c0 + cc);
            s_coef[rr * DSTRIDE + cc] =
                center_coef(vb[g], vb[NPIX + g], vb[2 * NPIX + g], sb[g]);
        }
        __syncthreads();
        const int j = j0 + jx;
        const int wc0 = max(j - R, 0), wc1 = min(j + R, WW - 1);
        float pm4[4];
        #pragma unroll
        for (int pi = 0; pi < 4; pi++) {
            int i = i0 + rgrp * 4 + pi;
            int wr0 = max(i - R, 0), wr1 = min(i + R, HH - 1);
            float m = BIGE;
            for (int r = wr0 + tz; r <= wr1; r += NPH) {
                float dx = (float)(i - r);
                float dx2 = dx * dx;
                const float4* row = s_coef + (r - r0) * DSTRIDE - c0;
                for (int cc = wc0; cc <= wc1; cc++) {
                    float4 k = row[cc];
                    float dy = (float)(j - cc);
                    float E = fmaf(k.x, dx2, k.w);
                    E = fmaf(k.y, dx * dy, E);
                    E = fmaf(k.z, dy * dy, E);
                    m = fminf(m, E);
                }
            }
            pm4[pi] = m;
        }
        float* pm = s_pmin + tz * PMW + rgrp * 80 + jx;
        pm[0] = pm4[0]; pm[16] = pm4[1]; pm[32] = pm4[2]; pm[48] = pm4[3];
    } else {
        // ---- slow path (never for sane inputs): full scan, on-the-fly coef ----
        const int j = j0 + jx;
        float pm4[4] = {BIGE, BIGE, BIGE, BIGE};
        for (int r = tz; r < HH; r += NPH) {
            float dxs[4];
            #pragma unroll
            for (int pi = 0; pi < 4; pi++) dxs[pi] = (float)(i0 + rgrp * 4 + pi - r);
            for (int cc = 0; cc < WW; cc++) {
                int g = r * WW + cc;
                float4 k = center_coef(vb[g], vb[NPIX + g], vb[2 * NPIX + g], sb[g]);
                float dy = (float)(j - cc);
                float s0 = fmaf(k.z, dy * dy, k.w);
                float t  = k.y * dy;
                #pragma unroll
                for (int pi = 0; pi < 4; pi++)
                    pm4[pi] = fminf(pm4[pi], fmaf(fmaf(k.x, dxs[pi], t), dxs[pi], s0));
            }
        }
        float* pm = s_pmin + tz * PMW + rgrp * 80 + jx;
        pm[0] = pm4[0]; pm[16] = pm4[1]; pm[32] = pm4[2]; pm[48] = pm4[3];
    }

    // ---- combine 16 phase partials per pixel, exp + threshold, store ----
    __syncthreads();
    if (tid < NPIXT) {
        int phys = tid + (tid >> 6) * 16;       // rgrp*80 + pi*16 + jx
        float m = s_pmin[phys];
        #pragma unroll
        for (int ph = 1; ph < NPH; ph++) m = fminf(m, s_pmin[ph * PMW + phys]);
        float pooled = __expf(1e-7f - m);       // exp(-minE + eps)
        int ti = tid >> 4, tj = tid & 15;
        out[(b * HH + i0 + ti) * WW + j0 + tj] = (pooled >= 0.7f) ? pooled : 0.0f;
    }
}

extern "C" void kernel_launch(void* const* d_in, const int* in_sizes, int n_in,
                              void* d_out, int out_size) {
    const float* var = (const float*)d_in[0];   // [2,3,80,80]
    const float* seg = (const float*)d_in[1];   // [2,1,80,80]
    float* out = (float*)d_out;                 // [2,1,80,80]
    fused_tile_kernel<<<dim3(WW / TW, HH / TH, BB), dim3(TW, 2, NPH)>>>(var, seg, out);
}